// round 8
// baseline (speedup 1.0000x reference)
#include <cuda_runtime.h>
#include <cstdint>

// L1Attn: out[b,i,j,h] = -(1/8) * sum_d |q[b,j,h,d] - k[b,i,h,d]|
// B=8, S=1024, H=8, D=64. Output [B,S,S,H] (i = keys, j = queries).
//
// Occupancy-focused: 3 blocks/SM (24 warps). Block = 8 i x 64 j x 8 h;
// thread = one h, 8 i x 2 j outputs, packed f32x2 math.
// k staged once (17 KB); q staged in 8-d chunks, double-buffered (2x24 KB)
// so staging overlaps compute with one barrier per chunk.

namespace {
constexpr int S  = 1024;
constexpr int H  = 8;
constexpr int D  = 64;
constexpr int NT = 256;
constexpr int TI = 8;     // i per block
constexpr int JB = 64;    // j per block (32 (w,jl) combos * 2 u)
constexpr int CD = 8;     // d per q chunk
constexpr int NC = D / CD;          // 8 chunks
constexpr int KROW = 68;            // k row pad: h-rows on distinct bank quads
constexpr int QROW = 12;            // q row: 8 d + 4 pad (quad step 3 -> conflict-free)
constexpr int QR   = JB * H;        // 512 q rows per chunk buffer
constexpr int KS_FLOATS = TI * H * KROW;      // 4352  (17408 B)
constexpr int QS_FLOATS = QR * QROW;          // 6144  (24576 B) per buffer
constexpr unsigned SMEM_BYTES = (KS_FLOATS + 2 * QS_FLOATS) * 4;  // 66560

typedef unsigned long long ull;

__device__ __forceinline__ ull addx2(ull a, ull b) {
    ull r;
    asm("add.rn.f32x2 %0, %1, %2;" : "=l"(r) : "l"(a), "l"(b));
    return r;
}
}  // namespace

__global__ void __launch_bounds__(NT, 3) l1attn_kernel(
    const float* __restrict__ qg,
    const float* __restrict__ kg,
    float* __restrict__ out)
{
    extern __shared__ __align__(16) float smf[];
    float* ks = smf;                         // [64 rows][68]
    float* qs0 = smf + KS_FLOATS;            // buffer 0: [512 rows][12]
    float* qs1 = qs0 + QS_FLOATS;            // buffer 1

    const int t  = threadIdx.x;
    const int j0 = blockIdx.x * JB;
    const int i0 = blockIdx.y * TI;
    const int b  = blockIdx.z;

    const float* qtile = qg + ((size_t)b * S + j0) * (size_t)(H * D);

    // ---- Stage k tile: rows (ii*8 + h), 64 floats each ----
    {
        const float* kb = kg + ((size_t)b * S + i0) * (size_t)(H * D);
        #pragma unroll
        for (int r = 0; r < (TI * H * D) / (4 * NT); r++) {  // 4 iters
            int idx = t + r * NT;
            int row = idx >> 4;
            int dd  = (idx & 15) << 2;
            float4 v = *reinterpret_cast<const float4*>(kb + row * D + dd);
            *reinterpret_cast<float4*>(&ks[row * KROW + dd]) = v;
        }
    }

    // ---- Stage q chunk 0 (d 0..7) into buffer 0 ----
    {
        #pragma unroll
        for (int r = 0; r < (QR * CD) / (4 * NT); r++) {  // 4 iters
            int p   = t + r * NT;       // float4 piece 0..1023
            int row = p >> 1;           // 0..511
            int sg  = p & 1;            // which 16B half of the 8-d slice
            float4 v = *reinterpret_cast<const float4*>(qtile + row * D + sg * 4);
            *reinterpret_cast<float4*>(&qs0[row * QROW + sg * 4]) = v;
        }
    }
    __syncthreads();

    const int h  = t & 7;
    const int jl = (t >> 3) & 3;
    const int w  = t >> 5;
    const int jbase = j0 + w * 4 + jl;           // (w,jl) -> j in [0,32); u adds 32 j
    const int qrow0 = (w * 4 + jl) * 8 + h;      // u adds 32 j = 256 rows

    const ull SGN = 0x8000000080000000ULL;
    const ull MSK = 0x7FFFFFFF7FFFFFFFULL;

    ull acc[TI][2];
    #pragma unroll
    for (int i = 0; i < TI; i++) { acc[i][0] = 0ULL; acc[i][1] = 0ULL; }

    #pragma unroll 1
    for (int c = 0; c < NC; c++) {
        float* qcur = (c & 1) ? qs1 : qs0;
        // ---- Prefetch next chunk into the other buffer (overlaps compute) ----
        if (c + 1 < NC) {
            float* qnxt = (c & 1) ? qs0 : qs1;
            const float* qgsrc = qtile + (c + 1) * CD;
            #pragma unroll
            for (int r = 0; r < (QR * CD) / (4 * NT); r++) {
                int p   = t + r * NT;
                int row = p >> 1;
                int sg  = p & 1;
                float4 v = *reinterpret_cast<const float4*>(qgsrc + row * D + sg * 4);
                *reinterpret_cast<float4*>(&qnxt[row * QROW + sg * 4]) = v;
            }
        }
        // ---- Compute on chunk c: 2 steps of 4 d ----
        #pragma unroll
        for (int s = 0; s < 2; s++) {
            ull nq[2][2];
            #pragma unroll
            for (int u = 0; u < 2; u++) {
                ulonglong2 qv = *reinterpret_cast<const ulonglong2*>(
                    qcur + (qrow0 + u * 256) * QROW + s * 4);
                nq[u][0] = qv.x ^ SGN;
                nq[u][1] = qv.y ^ SGN;
            }
            const float* kr = ks + h * KROW + c * CD + s * 4;
            #pragma unroll
            for (int i = 0; i < TI; i++) {
                ulonglong2 kv = *reinterpret_cast<const ulonglong2*>(kr + i * (8 * KROW));
                #pragma unroll
                for (int u = 0; u < 2; u++) {
                    ull t0 = addx2(kv.x, nq[u][0]) & MSK;   // |k-q| d pair 0
                    ull t1 = addx2(kv.y, nq[u][1]) & MSK;   // d pair 1
                    acc[i][u] = addx2(acc[i][u], addx2(t0, t1));
                }
            }
        }
        __syncthreads();   // STS of chunk c+1 drained; qcur reads done
    }

    // ---- Epilogue: reduce packed halves, scale, coalesced stores ----
    const float scale = -0.125f;  // -1/sqrt(64)
    #pragma unroll
    for (int i = 0; i < TI; i++) {
        const size_t ob = (((size_t)b * S + (i0 + i)) * S + jbase) * H + h;
        #pragma unroll
        for (int u = 0; u < 2; u++) {
            unsigned int lo = (unsigned int)(acc[i][u] & 0xffffffffu);
            unsigned int hi = (unsigned int)(acc[i][u] >> 32);
            out[ob + (size_t)u * (32 * H)] =
                (__uint_as_float(lo) + __uint_as_float(hi)) * scale;
        }
    }
}

extern "C" void kernel_launch(void* const* d_in, const int* in_sizes, int n_in,
                              void* d_out, int out_size) {
    const float* q = (const float*)d_in[0];
    const float* k = (const float*)d_in[1];
    float* out     = (float*)d_out;

    cudaFuncSetAttribute(l1attn_kernel,
                         cudaFuncAttributeMaxDynamicSharedMemorySize, SMEM_BYTES);

    const int B = in_sizes[0] / (S * H * D);  // = 8
    dim3 grid(S / JB, S / TI, B);
    l1attn_kernel<<<grid, NT, SMEM_BYTES>>>(q, k, out);
}

// round 10
// speedup vs baseline: 1.4058x; 1.4058x over previous
#include <cuda_runtime.h>
#include <cstdint>

// L1Attn: out[b,i,j,h] = -(1/8) * sum_d |q[b,j,h,d] - k[b,i,h,d]|
// B=8, S=1024, H=8, D=64. Output [B,S,S,H] (i = keys, j = queries).
//
// Block: 8 i x 128 j x 8 h. Thread: one h, 8 i x 4 j outputs, packed f32x2.
// k + q staged in smem (conflict-free padded layouts); q staged in 4 chunks
// of 16 d via cp.async (no register round-trip). s-loop fully unrolled so
// ptxas can hoist LDS above consumer math. sub.rn.f32x2 folds the negate.

namespace {
constexpr int S  = 1024;
constexpr int H  = 8;
constexpr int D  = 64;
constexpr int NT = 256;
constexpr int TI = 8;     // i per block
constexpr int JB = 128;   // j per block
constexpr int CD = 16;    // d per q chunk
constexpr int NC = D / CD;           // 4 chunks
constexpr int KROW = 68;             // k row: 64 d + 4 pad (h-rows distinct quads)
constexpr int QROW = 20;             // q row: 16 d + 4 pad (5*row mod 8 covers quads)
constexpr int KS_FLOATS = TI * H * KROW;   // 4352  (17408 B)
constexpr int QS_FLOATS = JB * H * QROW;   // 20480 (81920 B)
constexpr unsigned SMEM_BYTES = (KS_FLOATS + QS_FLOATS) * 4;  // 99328

typedef unsigned long long ull;

__device__ __forceinline__ ull subx2(ull a, ull b) {
    ull r;
    asm("sub.rn.f32x2 %0, %1, %2;" : "=l"(r) : "l"(a), "l"(b));
    return r;
}
__device__ __forceinline__ ull addx2(ull a, ull b) {
    ull r;
    asm("add.rn.f32x2 %0, %1, %2;" : "=l"(r) : "l"(a), "l"(b));
    return r;
}
__device__ __forceinline__ void cp16(uint32_t dst_smem, const float* src) {
    asm volatile("cp.async.cg.shared.global [%0], [%1], 16;"
                 :: "r"(dst_smem), "l"(src));
}
}  // namespace

__global__ void __launch_bounds__(NT, 2) l1attn_kernel(
    const float* __restrict__ qg,
    const float* __restrict__ kg,
    float* __restrict__ out)
{
    extern __shared__ __align__(16) float smf[];
    float* ks = smf;                // [64 rows][68]
    float* qs = smf + KS_FLOATS;    // [1024 rows][20], row = jj*8 + h

    const int t  = threadIdx.x;
    const int j0 = blockIdx.x * JB;
    const int i0 = blockIdx.y * TI;
    const int b  = blockIdx.z;

    const float* qtile = qg + ((size_t)b * S + j0) * (size_t)(H * D);
    const uint32_t qs_base = (uint32_t)__cvta_generic_to_shared(qs);

    // ---- Issue q chunk 0 staging (cp.async, reshaped into padded rows) ----
    #pragma unroll
    for (int r = 0; r < 16; r++) {
        int p   = t + r * NT;      // float4 piece 0..4095
        int row = p >> 2;          // 0..1023
        int sg  = p & 3;           // 16B seg within 16-d chunk
        cp16(qs_base + (row * QROW + sg * 4) * 4, qtile + row * D + sg * 4);
    }
    asm volatile("cp.async.commit_group;" ::: "memory");

    // ---- Stage k tile: rows (ii*8 + h), 64 floats each ----
    {
        const float* kb = kg + ((size_t)b * S + i0) * (size_t)(H * D);
        #pragma unroll
        for (int r = 0; r < (TI * H * D) / (4 * NT); r++) {  // 4 iters
            int idx = t + r * NT;
            int row = idx >> 4;
            int dd  = (idx & 15) << 2;
            float4 v = *reinterpret_cast<const float4*>(kb + row * D + dd);
            *reinterpret_cast<float4*>(&ks[row * KROW + dd]) = v;
        }
    }
    asm volatile("cp.async.wait_group 0;" ::: "memory");
    __syncthreads();

    const int h  = t & 7;
    const int jl = (t >> 3) & 3;
    const int w  = t >> 5;
    const int jbase = j0 + w * 16 + jl;          // u adds 4 j
    const int qrow0 = (w * 16 + jl) * 8 + h;     // u adds 4 j = 32 rows

    const ull MSK = 0x7FFFFFFF7FFFFFFFULL;

    ull acc[TI][4];
    #pragma unroll
    for (int i = 0; i < TI; i++)
        #pragma unroll
        for (int u = 0; u < 4; u++) acc[i][u] = 0ULL;

    #pragma unroll 1
    for (int cc = 0; cc < NC; cc++) {          // d-chunk of 16
        // ---- Compute on chunk cc (s fully unrolled: 4 steps of 4 d) ----
        #pragma unroll
        for (int s = 0; s < 4; s++) {
            ull qv[4][2];
            #pragma unroll
            for (int u = 0; u < 4; u++) {
                ulonglong2 q2 = *reinterpret_cast<const ulonglong2*>(
                    qs + (qrow0 + u * 32) * QROW + s * 4);
                qv[u][0] = q2.x;
                qv[u][1] = q2.y;
            }
            const float* kr = ks + h * KROW + cc * 16 + s * 4;
            #pragma unroll
            for (int i = 0; i < TI; i++) {
                ulonglong2 kv = *reinterpret_cast<const ulonglong2*>(kr + i * (8 * KROW));
                #pragma unroll
                for (int u = 0; u < 4; u++) {
                    ull t0 = subx2(kv.x, qv[u][0]) & MSK;   // |k-q| d pair 0
                    ull t1 = subx2(kv.y, qv[u][1]) & MSK;   // d pair 1
                    acc[i][u] = addx2(acc[i][u], addx2(t0, t1));
                }
            }
        }
        // ---- Stage next q chunk (single buffer: fence both sides) ----
        if (cc + 1 < NC) {
            __syncthreads();   // all reads of current chunk done
            const float* qc = qtile + (cc + 1) * CD;
            #pragma unroll
            for (int r = 0; r < 16; r++) {
                int p   = t + r * NT;
                int row = p >> 2;
                int sg  = p & 3;
                cp16(qs_base + (row * QROW + sg * 4) * 4, qc + row * D + sg * 4);
            }
            asm volatile("cp.async.commit_group;" ::: "memory");
            asm volatile("cp.async.wait_group 0;" ::: "memory");
            __syncthreads();
        }
    }

    // ---- Epilogue: reduce packed halves, scale, coalesced stores ----
    const float scale = -0.125f;  // -1/sqrt(64)
    #pragma unroll
    for (int i = 0; i < TI; i++) {
        const size_t ob = (((size_t)b * S + (i0 + i)) * S + jbase) * H + h;
        #pragma unroll
        for (int u = 0; u < 4; u++) {
            unsigned int lo = (unsigned int)(acc[i][u] & 0xffffffffu);
            unsigned int hi = (unsigned int)(acc[i][u] >> 32);
            out[ob + (size_t)u * (4 * H)] =
                (__uint_as_float(lo) + __uint_as_float(hi)) * scale;
        }
    }
}

extern "C" void kernel_launch(void* const* d_in, const int* in_sizes, int n_in,
                              void* d_out, int out_size) {
    const float* q = (const float*)d_in[0];
    const float* k = (const float*)d_in[1];
    float* out     = (float*)d_out;

    cudaFuncSetAttribute(l1attn_kernel,
                         cudaFuncAttributeMaxDynamicSharedMemorySize, SMEM_BYTES);

    const int B = in_sizes[0] / (S * H * D);  // = 8
    dim3 grid(S / JB, S / TI, B);
    l1attn_kernel<<<grid, NT, SMEM_BYTES>>>(q, k, out);
}